// round 2
// baseline (speedup 1.0000x reference)
#include <cuda_runtime.h>

#define THREADS     256
#define ATT_BLOCKS  2048
#define REC_BLOCKS  64
#define IDENT_BLOCKS 256
#define ATT_STRIDE  (ATT_BLOCKS * THREADS)   // 524288 float4 per iter
// total float4 = V*V*B*N*N/4 = 4*4*4*1024*1024/4 = 16777216 = ATT_STRIDE*32

__device__ float g_att_partial[ATT_BLOCKS];
__device__ float g_rec_sum[REC_BLOCKS];
__device__ float g_rec_cnt[REC_BLOCKS];
__device__ float g_rec_mn[3 * REC_BLOCKS];
__device__ float g_rec_mx[3 * REC_BLOCKS];
__device__ float g_ident[IDENT_BLOCKS];

__device__ __forceinline__ float softplus_f(float x) {
    // softplus(x) = max(x,0) + log(1 + exp(-|x|))
    return fmaxf(x, 0.f) + __logf(1.f + __expf(-fabsf(x)));
}

// ---------------------------------------------------------------------------
// Attention loss: sum over corr [V,V,B,N,N] of
//   w * (max(x,0) - x*gt + log1p(exp(-|x|))),  gt = band(|i-j|) * (vis_i | vis_j)
// band nonzero only for |i-j| <= 2 -> rare warp-coherent branch.
// ---------------------------------------------------------------------------
__global__ void att_kernel(const float4* __restrict__ corr, const int* __restrict__ vis) {
    __shared__ unsigned char vsm[4][1024];
    for (int t = threadIdx.x; t < 4096; t += THREADS) {
        int bb = t >> 10, n = t & 1023;
        vsm[bb][n] = (vis[bb * 16384 + n] > 0) ? 1 : 0;   // visibility[b, 0, n]
    }
    __syncthreads();

    float acc = 0.f;
    unsigned base = blockIdx.x * THREADS + threadIdx.x;
#pragma unroll 4
    for (int it = 0; it < 32; ++it) {
        unsigned g = base + (unsigned)it * ATT_STRIDE;
        float4 x = corr[g];
        float t0 = softplus_f(x.x);
        float t1 = softplus_f(x.y);
        float t2 = softplus_f(x.z);
        float t3 = softplus_f(x.w);

        unsigned j0 = (g & 255u) << 2;       // element index e = 4g; j = e & 1023
        unsigned i  = (g >> 8) & 1023u;      // i = (e >> 10) & 1023
        if (i + 2u - j0 <= 7u) {             // any j in [j0, j0+3] with |i-j| <= 2
            unsigned bb = (g >> 18) & 3u;    // b = (e >> 20) & 3
            float vi = (float)vsm[bb][i];
            float xs[4] = {x.x, x.y, x.z, x.w};
            float ts[4] = {t0, t1, t2, t3};
#pragma unroll
            for (int k = 0; k < 4; ++k) {
                int j = (int)j0 + k;
                int d = abs((int)i - j);
                float band = (d == 0) ? 1.f : (d == 1) ? 0.7f : (d == 2) ? 0.49f : 0.f;
                float pair = (vi > 0.f || vsm[bb][j]) ? 1.f : 0.f;
                float gt = band * pair;
                float u = ts[k] - xs[k] * gt;       // max(x,0) - x*gt + log1p(exp(-|x|))
                ts[k] = fmaf(2.f * gt, u, u);       // (1 + 2*gt) * u
            }
            t0 = ts[0]; t1 = ts[1]; t2 = ts[2]; t3 = ts[3];
        }
        acc += (t0 + t1) + (t2 + t3);
    }

    __shared__ float red[THREADS];
    red[threadIdx.x] = acc;
    __syncthreads();
    for (int s = THREADS / 2; s > 0; s >>= 1) {
        if (threadIdx.x < s) red[threadIdx.x] += red[threadIdx.x + s];
        __syncthreads();
    }
    if (threadIdx.x == 0) g_att_partial[blockIdx.x] = red[0];
}

// ---------------------------------------------------------------------------
// Reconstruction loss partials: masked SE sum, masked count, masked min/max of gt per coord
// ---------------------------------------------------------------------------
__global__ void rec_kernel(const float* __restrict__ rp, const float* __restrict__ gp,
                           const int* __restrict__ vis) {
    int tid = blockIdx.x * THREADS + threadIdx.x;
    float sum = 0.f, cnt = 0.f;
    float mn0 = 1e30f, mn1 = 1e30f, mn2 = 1e30f;
    float mx0 = -1e30f, mx1 = -1e30f, mx2 = -1e30f;
    for (int p = tid; p < 65536; p += REC_BLOCKS * THREADS) {
        if (vis[p] > 0) {
            float g0 = gp[3 * p], g1 = gp[3 * p + 1], g2 = gp[3 * p + 2];
            float d0 = rp[3 * p] - g0, d1 = rp[3 * p + 1] - g1, d2 = rp[3 * p + 2] - g2;
            sum += d0 * d0 + d1 * d1 + d2 * d2;
            cnt += 1.f;
            mn0 = fminf(mn0, g0); mn1 = fminf(mn1, g1); mn2 = fminf(mn2, g2);
            mx0 = fmaxf(mx0, g0); mx1 = fmaxf(mx1, g1); mx2 = fmaxf(mx2, g2);
        }
    }
    __shared__ float red[THREADS];
    int t = threadIdx.x;
#define BRED(var, OP, dst)                                            \
    red[t] = var; __syncthreads();                                    \
    for (int s = THREADS / 2; s > 0; s >>= 1) {                       \
        if (t < s) red[t] = OP(red[t], red[t + s]);                   \
        __syncthreads();                                              \
    }                                                                 \
    if (t == 0) dst = red[0];                                         \
    __syncthreads();
#define ADDOP(a, b) ((a) + (b))
    BRED(sum, ADDOP, g_rec_sum[blockIdx.x]);
    BRED(cnt, ADDOP, g_rec_cnt[blockIdx.x]);
    BRED(mn0, fminf, g_rec_mn[0 * REC_BLOCKS + blockIdx.x]);
    BRED(mn1, fminf, g_rec_mn[1 * REC_BLOCKS + blockIdx.x]);
    BRED(mn2, fminf, g_rec_mn[2 * REC_BLOCKS + blockIdx.x]);
    BRED(mx0, fmaxf, g_rec_mx[0 * REC_BLOCKS + blockIdx.x]);
    BRED(mx1, fmaxf, g_rec_mx[1 * REC_BLOCKS + blockIdx.x]);
    BRED(mx2, fmaxf, g_rec_mx[2 * REC_BLOCKS + blockIdx.x]);
#undef BRED
#undef ADDOP
}

// ---------------------------------------------------------------------------
// Identity loss: one block per (v,b,f). Phase 1: track min/max over n -> wh.
// Phase 2: project (LTR FMA chain, matching XLA contraction order), IEEE
// divisions in the sensitive path, error sum. g_ident[blk] = mean over n.
// ---------------------------------------------------------------------------
__global__ void ident_kernel(const float* __restrict__ pred, const float* __restrict__ proj,
                             const float* __restrict__ tracks) {
    int blk = blockIdx.x;
    int v = blk >> 6;           // / (B*F) = 64
    int b = (blk >> 4) & 3;     // / F % B
    int f = blk & 15;
    int t = threadIdx.x;

    __shared__ float P[12];
    if (t < 12) P[t] = proj[(v * 4 + b) * 12 + t];

    const float* tr = tracks + (size_t)(((v * 4 + b) * 16 + f) * 1024) * 2;
    const float* pp = pred + (size_t)((b * 16 + f) * 1024) * 3;

    float mn0 = 1e30f, mn1 = 1e30f, mx0 = -1e30f, mx1 = -1e30f;
    for (int n = t; n < 1024; n += THREADS) {
        float a0 = tr[2 * n], a1 = tr[2 * n + 1];
        if (fabsf(a0) + fabsf(a1) > 1e-6f) {
            mn0 = fminf(mn0, a0); mn1 = fminf(mn1, a1);
            mx0 = fmaxf(mx0, a0); mx1 = fmaxf(mx1, a1);
        }
    }

    __shared__ float red[THREADS];
    __shared__ float swh[2];
#define BRED2(var, OP, dst)                                           \
    red[t] = var; __syncthreads();                                    \
    for (int s = THREADS / 2; s > 0; s >>= 1) {                       \
        if (t < s) red[t] = OP(red[t], red[t + s]);                   \
        __syncthreads();                                              \
    }                                                                 \
    if (t == 0) dst = red[0];                                         \
    __syncthreads();
    __shared__ float sres[4];
    BRED2(mn0, fminf, sres[0]);
    BRED2(mn1, fminf, sres[1]);
    BRED2(mx0, fmaxf, sres[2]);
    BRED2(mx1, fmaxf, sres[3]);
    if (t == 0) {
        // if no valid point: mx-mn = -2e30 -> max(224, ...) = 224, matching reference
        swh[0] = fmaxf(224.0f, sres[2] - sres[0] + 1e-6f);
        swh[1] = fmaxf(224.0f, sres[3] - sres[1] + 1e-6f);
    }
    __syncthreads();
    float wh0 = swh[0], wh1 = swh[1];

    float s = 0.f;
    for (int n = t; n < 1024; n += THREADS) {
        float px = pp[3 * n], py = pp[3 * n + 1], pz = pp[3 * n + 2];
        // Left-to-right FMA contraction over j, matching XLA's k-loop:
        //   s = P0*x; s = fma(P1,y,s); s = fma(P2,z,s); s = s + P3
        float h0 = __fmul_rn(P[0], px);
        h0 = __fmaf_rn(P[1], py, h0);
        h0 = __fmaf_rn(P[2], pz, h0);
        h0 = __fadd_rn(h0, P[3]);
        float h1 = __fmul_rn(P[4], px);
        h1 = __fmaf_rn(P[5], py, h1);
        h1 = __fmaf_rn(P[6], pz, h1);
        h1 = __fadd_rn(h1, P[7]);
        float h2 = __fmul_rn(P[8], px);
        h2 = __fmaf_rn(P[9], py, h2);
        h2 = __fmaf_rn(P[10], pz, h2);
        h2 = __fadd_rn(h2, P[11]);

        float d = __fadd_rn(h2, 1e-10f);
        float p20 = __fdiv_rn(h0, d);     // IEEE division: matches reference exactly
        float p21 = __fdiv_rn(h1, d);
        float a0 = tr[2 * n], a1 = tr[2 * n + 1];
        float e0 = __fdiv_rn(__fadd_rn(p20, -a0), wh0);
        float e1 = __fdiv_rn(__fadd_rn(p21, -a1), wh1);
        s += __fmul_rn(e0, e0) + __fmul_rn(e1, e1);
    }
#define ADDOP2(a, b) ((a) + (b))
    BRED2(s, ADDOP2, g_ident[blk]);
#undef BRED2
#undef ADDOP2
    if (t == 0) g_ident[blk] *= (1.0f / 1024.0f);
}

// ---------------------------------------------------------------------------
// Final combine (deterministic fixed-order reductions)
// ---------------------------------------------------------------------------
__global__ void final_kernel(float* __restrict__ out) {
    int tid = threadIdx.x;
    __shared__ float red[THREADS];

    // attention
    float a = 0.f;
    for (int k = tid; k < ATT_BLOCKS; k += THREADS) a += g_att_partial[k];
    red[tid] = a; __syncthreads();
    for (int s = THREADS / 2; s > 0; s >>= 1) {
        if (tid < s) red[tid] += red[tid + s];
        __syncthreads();
    }
    float att = red[0] * (1.0f / 67108864.0f);
    __syncthreads();

    // identity
    red[tid] = g_ident[tid]; __syncthreads();
    for (int s = THREADS / 2; s > 0; s >>= 1) {
        if (tid < s) red[tid] += red[tid + s];
        __syncthreads();
    }
    float ident = red[0] * (1.0f / 256.0f);
    __syncthreads();

    // reconstruction: sum, cnt
    red[tid] = (tid < REC_BLOCKS) ? g_rec_sum[tid] : 0.f; __syncthreads();
    for (int s = THREADS / 2; s > 0; s >>= 1) {
        if (tid < s) red[tid] += red[tid + s];
        __syncthreads();
    }
    float recSum = red[0]; __syncthreads();

    red[tid] = (tid < REC_BLOCKS) ? g_rec_cnt[tid] : 0.f; __syncthreads();
    for (int s = THREADS / 2; s > 0; s >>= 1) {
        if (tid < s) red[tid] += red[tid + s];
        __syncthreads();
    }
    float cnt = red[0]; __syncthreads();

    float mn[3], mx[3];
#pragma unroll
    for (int c = 0; c < 3; ++c) {
        red[tid] = (tid < REC_BLOCKS) ? g_rec_mn[c * REC_BLOCKS + tid] : 1e30f; __syncthreads();
        for (int s = THREADS / 2; s > 0; s >>= 1) {
            if (tid < s) red[tid] = fminf(red[tid], red[tid + s]);
            __syncthreads();
        }
        mn[c] = red[0]; __syncthreads();
        red[tid] = (tid < REC_BLOCKS) ? g_rec_mx[c * REC_BLOCKS + tid] : -1e30f; __syncthreads();
        for (int s = THREADS / 2; s > 0; s >>= 1) {
            if (tid < s) red[tid] = fmaxf(red[tid], red[tid + s]);
            __syncthreads();
        }
        mx[c] = red[0]; __syncthreads();
    }

    if (tid == 0) {
        float num = cnt * 3.0f;
        float mse = recSum / fmaxf(num, 1.0f);
        float sc = fmaxf(fmaxf(mx[0] - mn[0], mx[1] - mn[1]), mx[2] - mn[2]) + 1e-6f;
        if (!(num > 0.f)) sc = 1.0f;
        float rec = mse / (sc * sc);
        float total = rec + ident + 0.5f * att;
        out[0] = total;
        out[1] = rec;
        out[2] = ident;
        out[3] = att;
    }
}

extern "C" void kernel_launch(void* const* d_in, const int* in_sizes, int n_in,
                              void* d_out, int out_size) {
    const float*  rp     = (const float*)d_in[0];   // refined_points [4,16,1024,3]
    const float*  gp     = (const float*)d_in[1];   // gt_points
    const int*    vis    = (const int*)d_in[2];     // visibility [4,16,1024]
    const float*  proj   = (const float*)d_in[3];   // projection [4,4,3,4]
    const float*  tracks = (const float*)d_in[4];   // tracks_2d [4,4,16,1024,2]
    const float4* corr   = (const float4*)d_in[5];  // corr [4,4,4,1024,1024]

    att_kernel<<<ATT_BLOCKS, THREADS>>>(corr, vis);
    rec_kernel<<<REC_BLOCKS, THREADS>>>(rp, gp, vis);
    ident_kernel<<<IDENT_BLOCKS, THREADS>>>(rp, proj, tracks);
    final_kernel<<<1, THREADS>>>((float*)d_out);
}